// round 1
// baseline (speedup 1.0000x reference)
#include <cuda_runtime.h>
#include <math.h>

// Problem constants
#define Bb   2
#define Ss   2048
#define Ee   768
#define Hh   12
#define Dd   64
#define FFf  3072
#define Mrows (Bb*Ss)   // 4096

// ---------------------------------------------------------------------------
// Scratch (static device globals; no runtime allocation allowed)
// ---------------------------------------------------------------------------
__device__ float g_xn [Mrows*Ee];
__device__ float g_q  [Mrows*Ee];
__device__ float g_k  [Mrows*Ee];
__device__ float g_v  [Mrows*Ee];
__device__ float g_at [Mrows*Ee];
__device__ float g_res[Mrows*Ee];
__device__ float g_y  [Mrows*Ee];
__device__ float g_h  [Mrows*FFf];

// ---------------------------------------------------------------------------
// LayerNorm: one block (256 threads) per row of 768
// ---------------------------------------------------------------------------
__global__ void ln_kernel(const float* __restrict__ X,
                          const float* __restrict__ gamma,
                          const float* __restrict__ beta,
                          float* __restrict__ Y)
{
    const int row = blockIdx.x;
    const float* x = X + (size_t)row * Ee;
    float*       y = Y + (size_t)row * Ee;
    const int t = threadIdx.x;   // 256 threads, 3 elems each

    float v0 = x[t], v1 = x[t + 256], v2 = x[t + 512];
    float s  = v0 + v1 + v2;

    __shared__ float red[8];
    #pragma unroll
    for (int off = 16; off; off >>= 1) s += __shfl_xor_sync(0xffffffffu, s, off);
    if ((t & 31) == 0) red[t >> 5] = s;
    __syncthreads();
    if (t < 8) {
        float r = red[t];
        #pragma unroll
        for (int off = 4; off; off >>= 1) r += __shfl_xor_sync(0xffu, r, off);
        if (t == 0) red[0] = r;
    }
    __syncthreads();
    const float mu = red[0] * (1.0f / Ee);
    __syncthreads();   // red[] reused below

    float d0 = v0 - mu, d1 = v1 - mu, d2 = v2 - mu;
    float q  = d0*d0 + d1*d1 + d2*d2;
    #pragma unroll
    for (int off = 16; off; off >>= 1) q += __shfl_xor_sync(0xffffffffu, q, off);
    if ((t & 31) == 0) red[t >> 5] = q;
    __syncthreads();
    if (t < 8) {
        float r = red[t];
        #pragma unroll
        for (int off = 4; off; off >>= 1) r += __shfl_xor_sync(0xffu, r, off);
        if (t == 0) red[0] = r;
    }
    __syncthreads();
    const float inv = rsqrtf(red[0] * (1.0f / Ee) + 1e-5f);

    y[t      ] = d0 * inv * gamma[t      ] + beta[t      ];
    y[t + 256] = d1 * inv * gamma[t + 256] + beta[t + 256];
    y[t + 512] = d2 * inv * gamma[t + 512] + beta[t + 512];
}

// ---------------------------------------------------------------------------
// SGEMM: C[M,N] = A[M,K] * B[N,K]^T  (+ epilogue)
// 128x128x16 tile, 256 threads, 8x8 per-thread microtile
// ---------------------------------------------------------------------------
enum { EPI_NONE = 0, EPI_BIAS = 1, EPI_BIAS_GELU = 2, EPI_BIAS_RES = 3 };

template <int EPI>
__global__ __launch_bounds__(256, 2)
void sgemm_bt(const float* __restrict__ A, const float* __restrict__ Bm,
              const float* __restrict__ bias, const float* __restrict__ R,
              float* __restrict__ C, int M, int N, int K)
{
    __shared__ float As[16][128];
    __shared__ float Bs[16][128];

    const int bm = blockIdx.y * 128;
    const int bn = blockIdx.x * 128;
    const int t  = threadIdx.x;
    const int ty = t >> 4, tx = t & 15;
    const int lr = t >> 2;          // 0..63
    const int lc = (t & 3) * 4;     // 0,4,8,12

    const float* Ap = A  + (size_t)(bm + lr) * K + lc;
    const float* Bp = Bm + (size_t)(bn + lr) * K + lc;

    float acc[8][8];
    #pragma unroll
    for (int i = 0; i < 8; i++)
        #pragma unroll
        for (int j = 0; j < 8; j++) acc[i][j] = 0.f;

    for (int k0 = 0; k0 < K; k0 += 16) {
        #pragma unroll
        for (int rr = 0; rr < 2; rr++) {
            float4 va = *(const float4*)(Ap + (size_t)rr * 64 * K + k0);
            As[lc + 0][lr + rr*64] = va.x; As[lc + 1][lr + rr*64] = va.y;
            As[lc + 2][lr + rr*64] = va.z; As[lc + 3][lr + rr*64] = va.w;
            float4 vb = *(const float4*)(Bp + (size_t)rr * 64 * K + k0);
            Bs[lc + 0][lr + rr*64] = vb.x; Bs[lc + 1][lr + rr*64] = vb.y;
            Bs[lc + 2][lr + rr*64] = vb.z; Bs[lc + 3][lr + rr*64] = vb.w;
        }
        __syncthreads();
        #pragma unroll
        for (int kk = 0; kk < 16; kk++) {
            float4 a0 = *(const float4*)&As[kk][ty * 4];
            float4 a1 = *(const float4*)&As[kk][64 + ty * 4];
            float4 b0 = *(const float4*)&Bs[kk][tx * 4];
            float4 b1 = *(const float4*)&Bs[kk][64 + tx * 4];
            float a[8] = {a0.x,a0.y,a0.z,a0.w,a1.x,a1.y,a1.z,a1.w};
            float b[8] = {b0.x,b0.y,b0.z,b0.w,b1.x,b1.y,b1.z,b1.w};
            #pragma unroll
            for (int i = 0; i < 8; i++)
                #pragma unroll
                for (int j = 0; j < 8; j++)
                    acc[i][j] = fmaf(a[i], b[j], acc[i][j]);
        }
        __syncthreads();
    }

    #pragma unroll
    for (int i = 0; i < 8; i++) {
        const int row = bm + ((i < 4) ? (ty * 4 + i) : (64 + ty * 4 + i - 4));
        #pragma unroll
        for (int j = 0; j < 8; j++) {
            const int col = bn + ((j < 4) ? (tx * 4 + j) : (64 + tx * 4 + j - 4));
            float v = acc[i][j];
            if (EPI >= EPI_BIAS)      v += bias[col];
            if (EPI == EPI_BIAS_GELU) v = 0.5f * v * (1.0f + erff(v * 0.70710678118654752f));
            if (EPI == EPI_BIAS_RES)  v += R[(size_t)row * N + col];
            C[(size_t)row * N + col] = v;
        }
    }
}

// ---------------------------------------------------------------------------
// Flash attention (fp32, causal, online softmax)
// Block: 256 threads, 64 queries of one (b,h); 64-wide K/V tiles
// smem: Qs[64][68], Kt[64][68] (d-major), Vs[64][68], Ps[64][68]  (~69.6 KB dyn)
// ---------------------------------------------------------------------------
#define LDA 68
__global__ __launch_bounds__(256, 2)
void flash_kernel(const float* __restrict__ Qg, const float* __restrict__ Kg,
                  const float* __restrict__ Vg, float* __restrict__ Og)
{
    extern __shared__ float sm[];
    float* Qs = sm;
    float* Kt = sm + 64 * LDA;
    float* Vs = sm + 2 * 64 * LDA;
    float* Ps = sm + 3 * 64 * LDA;

    const int qt = blockIdx.x, h = blockIdx.y, b = blockIdx.z;
    const int q0 = qt * 64;
    const int t  = threadIdx.x;
    const int ty = t >> 4, tx = t & 15;
    const int lr = t >> 2, lq = t & 3;
    const size_t base = (size_t)b * Ss * Ee + h * Dd;

    // Load Q tile once
    {
        const float* qp = Qg + base + (size_t)(q0 + lr) * Ee;
        #pragma unroll
        for (int c = 0; c < 4; c++) {
            const int col = (c * 4 + lq) * 4;
            *(float4*)&Qs[lr * LDA + col] = *(const float4*)(qp + col);
        }
    }

    float m[4], l[4], o[4][4];
    #pragma unroll
    for (int i = 0; i < 4; i++) {
        m[i] = -INFINITY; l[i] = 0.f;
        #pragma unroll
        for (int j = 0; j < 4; j++) o[i][j] = 0.f;
    }
    __syncthreads();

    for (int kt = 0; kt <= qt; kt++) {
        const int k0 = kt * 64;
        // Load K (transposed -> d-major) and V (row-major)
        {
            const float* kp = Kg + base + (size_t)(k0 + lr) * Ee;
            const float* vp = Vg + base + (size_t)(k0 + lr) * Ee;
            #pragma unroll
            for (int c = 0; c < 4; c++) {
                const int col = (c * 4 + lq) * 4;
                float4 kv = *(const float4*)(kp + col);
                Kt[(col + 0) * LDA + lr] = kv.x;
                Kt[(col + 1) * LDA + lr] = kv.y;
                Kt[(col + 2) * LDA + lr] = kv.z;
                Kt[(col + 3) * LDA + lr] = kv.w;
                *(float4*)&Vs[lr * LDA + col] = *(const float4*)(vp + col);
            }
        }
        __syncthreads();

        // Scores: s[i][j] = sum_d Q[i][d] * K[j][d]
        float s[4][4];
        #pragma unroll
        for (int i = 0; i < 4; i++)
            #pragma unroll
            for (int j = 0; j < 4; j++) s[i][j] = 0.f;

        #pragma unroll
        for (int d4 = 0; d4 < 16; d4++) {
            float qa[4][4], ka[4][4];
            #pragma unroll
            for (int i = 0; i < 4; i++) {
                float4 v = *(const float4*)&Qs[(ty * 4 + i) * LDA + d4 * 4];
                qa[i][0] = v.x; qa[i][1] = v.y; qa[i][2] = v.z; qa[i][3] = v.w;
            }
            #pragma unroll
            for (int dd = 0; dd < 4; dd++) {
                float4 v = *(const float4*)&Kt[(d4 * 4 + dd) * LDA + tx * 4];
                ka[dd][0] = v.x; ka[dd][1] = v.y; ka[dd][2] = v.z; ka[dd][3] = v.w;
            }
            #pragma unroll
            for (int dd = 0; dd < 4; dd++)
                #pragma unroll
                for (int i = 0; i < 4; i++)
                    #pragma unroll
                    for (int j = 0; j < 4; j++)
                        s[i][j] = fmaf(qa[i][dd], ka[dd][j], s[i][j]);
        }

        // Scale + causal mask + online softmax update
        const bool diag = (kt == qt);
        #pragma unroll
        for (int i = 0; i < 4; i++) {
            const int qi = ty * 4 + i;   // local query row
            #pragma unroll
            for (int j = 0; j < 4; j++) {
                float val = s[i][j] * 0.125f;    // 1/sqrt(64)
                if (diag && (tx * 4 + j) > qi) val = -1e30f;
                s[i][j] = val;
            }
            float tm = fmaxf(fmaxf(s[i][0], s[i][1]), fmaxf(s[i][2], s[i][3]));
            #pragma unroll
            for (int off = 8; off; off >>= 1)
                tm = fmaxf(tm, __shfl_xor_sync(0xffffffffu, tm, off));
            const float mn    = fmaxf(m[i], tm);
            const float alpha = __expf(m[i] - mn);
            float rs = 0.f;
            #pragma unroll
            for (int j = 0; j < 4; j++) {
                float p = __expf(s[i][j] - mn);
                s[i][j] = p; rs += p;
            }
            #pragma unroll
            for (int off = 8; off; off >>= 1)
                rs += __shfl_xor_sync(0xffffffffu, rs, off);
            l[i] = l[i] * alpha + rs;
            m[i] = mn;
            #pragma unroll
            for (int j = 0; j < 4; j++) o[i][j] *= alpha;
        }

        // Store P tile
        #pragma unroll
        for (int i = 0; i < 4; i++)
            *(float4*)&Ps[(ty * 4 + i) * LDA + tx * 4] =
                make_float4(s[i][0], s[i][1], s[i][2], s[i][3]);
        __syncthreads();

        // O += P @ V
        #pragma unroll
        for (int j4 = 0; j4 < 16; j4++) {
            float pa[4][4], va[4][4];
            #pragma unroll
            for (int i = 0; i < 4; i++) {
                float4 v = *(const float4*)&Ps[(ty * 4 + i) * LDA + j4 * 4];
                pa[i][0] = v.x; pa[i][1] = v.y; pa[i][2] = v.z; pa[i][3] = v.w;
            }
            #pragma unroll
            for (int jj = 0; jj < 4; jj++) {
                float4 v = *(const float4*)&Vs[(j4 * 4 + jj) * LDA + tx * 4];
                va[jj][0] = v.x; va[jj][1] = v.y; va[jj][2] = v.z; va[jj][3] = v.w;
            }
            #pragma unroll
            for (int jj = 0; jj < 4; jj++)
                #pragma unroll
                for (int i = 0; i < 4; i++)
                    #pragma unroll
                    for (int d = 0; d < 4; d++)
                        o[i][d] = fmaf(pa[i][jj], va[jj][d], o[i][d]);
        }
        __syncthreads();
    }

    // Normalize + write
    #pragma unroll
    for (int i = 0; i < 4; i++) {
        const float inv = 1.0f / l[i];
        const int row = q0 + ty * 4 + i;
        float* op = Og + base + (size_t)row * Ee + tx * 4;
        op[0] = o[i][0] * inv; op[1] = o[i][1] * inv;
        op[2] = o[i][2] * inv; op[3] = o[i][3] * inv;
    }
}

// ---------------------------------------------------------------------------
// Launch: LN -> QKV GEMMs -> flash attn -> O proj(+res) -> LN -> FFN1(GELU) -> FFN2(+res)
// ---------------------------------------------------------------------------
extern "C" void kernel_launch(void* const* d_in, const int* in_sizes, int n_in,
                              void* d_out, int out_size)
{
    const float* x     = (const float*)d_in[0];
    const float* wq    = (const float*)d_in[1];
    const float* wk    = (const float*)d_in[2];
    const float* wv    = (const float*)d_in[3];
    const float* wo    = (const float*)d_in[4];
    const float* bo    = (const float*)d_in[5];
    const float* w1    = (const float*)d_in[6];
    const float* b1    = (const float*)d_in[7];
    const float* w2    = (const float*)d_in[8];
    const float* b2    = (const float*)d_in[9];
    const float* gamma = (const float*)d_in[10];
    const float* beta  = (const float*)d_in[11];
    float* out = (float*)d_out;

    float *xn, *q, *k, *v, *at, *res, *y, *hb;
    cudaGetSymbolAddress((void**)&xn,  g_xn);
    cudaGetSymbolAddress((void**)&q,   g_q);
    cudaGetSymbolAddress((void**)&k,   g_k);
    cudaGetSymbolAddress((void**)&v,   g_v);
    cudaGetSymbolAddress((void**)&at,  g_at);
    cudaGetSymbolAddress((void**)&res, g_res);
    cudaGetSymbolAddress((void**)&y,   g_y);
    cudaGetSymbolAddress((void**)&hb,  g_h);

    const dim3 g768(Ee / 128, Mrows / 128);    // (6, 32)
    const dim3 g3072(FFf / 128, Mrows / 128);  // (24, 32)
    const int  smemFA = 4 * 64 * LDA * (int)sizeof(float);

    cudaFuncSetAttribute(flash_kernel, cudaFuncAttributeMaxDynamicSharedMemorySize, smemFA);

    ln_kernel<<<Mrows, 256>>>(x, gamma, beta, xn);

    sgemm_bt<EPI_NONE><<<g768, 256>>>(xn, wq, nullptr, nullptr, q, Mrows, Ee, Ee);
    sgemm_bt<EPI_NONE><<<g768, 256>>>(xn, wk, nullptr, nullptr, k, Mrows, Ee, Ee);
    sgemm_bt<EPI_NONE><<<g768, 256>>>(xn, wv, nullptr, nullptr, v, Mrows, Ee, Ee);

    flash_kernel<<<dim3(Ss / 64, Hh, Bb), 256, smemFA>>>(q, k, v, at);

    sgemm_bt<EPI_BIAS_RES><<<g768, 256>>>(at, wo, bo, x, res, Mrows, Ee, Ee);

    ln_kernel<<<Mrows, 256>>>(res, gamma, beta, y);

    sgemm_bt<EPI_BIAS_GELU><<<g3072, 256>>>(y, w1, b1, nullptr, hb, Mrows, FFf, Ee);
    sgemm_bt<EPI_BIAS_RES><<<g768, 256>>>(hb, w2, b2, res, out, Mrows, Ee, FFf);
}

// round 2
// speedup vs baseline: 1.2039x; 1.2039x over previous
#include <cuda_runtime.h>
#include <math.h>

// Problem constants
#define Bb   2
#define Ss   2048
#define Ee   768
#define Hh   12
#define Dd   64
#define FFf  3072
#define Mrows (Bb*Ss)   // 4096

// ---------------------------------------------------------------------------
// Scratch (static device globals; no runtime allocation allowed)
// ---------------------------------------------------------------------------
__device__ float g_xn [Mrows*Ee];
__device__ float g_q  [Mrows*Ee];
__device__ float g_k  [Mrows*Ee];
__device__ float g_v  [Mrows*Ee];
__device__ float g_at [Mrows*Ee];
__device__ float g_res[Mrows*Ee];
__device__ float g_y  [Mrows*Ee];
__device__ float g_h  [Mrows*FFf];

// ---------------------------------------------------------------------------
// LayerNorm: one block (256 threads) per row of 768
// ---------------------------------------------------------------------------
__global__ void ln_kernel(const float* __restrict__ X,
                          const float* __restrict__ gamma,
                          const float* __restrict__ beta,
                          float* __restrict__ Y)
{
    const int row = blockIdx.x;
    const float* x = X + (size_t)row * Ee;
    float*       y = Y + (size_t)row * Ee;
    const int t = threadIdx.x;   // 256 threads, 3 elems each

    float v0 = x[t], v1 = x[t + 256], v2 = x[t + 512];
    float s  = v0 + v1 + v2;

    __shared__ float red[8];
    #pragma unroll
    for (int off = 16; off; off >>= 1) s += __shfl_xor_sync(0xffffffffu, s, off);
    if ((t & 31) == 0) red[t >> 5] = s;
    __syncthreads();
    if (t < 8) {
        float r = red[t];
        #pragma unroll
        for (int off = 4; off; off >>= 1) r += __shfl_xor_sync(0xffu, r, off);
        if (t == 0) red[0] = r;
    }
    __syncthreads();
    const float mu = red[0] * (1.0f / Ee);
    __syncthreads();   // red[] reused below

    float d0 = v0 - mu, d1 = v1 - mu, d2 = v2 - mu;
    float q  = d0*d0 + d1*d1 + d2*d2;
    #pragma unroll
    for (int off = 16; off; off >>= 1) q += __shfl_xor_sync(0xffffffffu, q, off);
    if ((t & 31) == 0) red[t >> 5] = q;
    __syncthreads();
    if (t < 8) {
        float r = red[t];
        #pragma unroll
        for (int off = 4; off; off >>= 1) r += __shfl_xor_sync(0xffu, r, off);
        if (t == 0) red[0] = r;
    }
    __syncthreads();
    const float inv = rsqrtf(red[0] * (1.0f / Ee) + 1e-5f);

    y[t      ] = d0 * inv * gamma[t      ] + beta[t      ];
    y[t + 256] = d1 * inv * gamma[t + 256] + beta[t + 256];
    y[t + 512] = d2 * inv * gamma[t + 512] + beta[t + 512];
}

// ---------------------------------------------------------------------------
// SGEMM: C[M,N] = A[M,K] * B[N,K]^T  (+ epilogue)
// 128x128x16 tile, 256 threads, 8x8 per-thread microtile.
// Double-buffered smem, global prefetch pipelined across K-steps,
// one __syncthreads per K-step.
// NQKV=3: gridDim.z selects (Bq,Cq)/(Bk,Ck)/(Bv,Cv) for a fused QKV launch.
// ---------------------------------------------------------------------------
enum { EPI_NONE = 0, EPI_BIAS = 1, EPI_BIAS_GELU = 2, EPI_BIAS_RES = 3 };

#define SLD 132   // smem row pitch (floats); 132*4B = 528B, 16B-aligned rows

template <int EPI, int NQKV>
__global__ __launch_bounds__(256, 2)
void sgemm_bt(const float* __restrict__ A,
              const float* __restrict__ Bq, const float* __restrict__ Bk,
              const float* __restrict__ Bv,
              const float* __restrict__ bias, const float* __restrict__ R,
              float* __restrict__ Cq, float* __restrict__ Ck,
              float* __restrict__ Cv,
              int M, int N, int K)
{
    const float* Bm = Bq;
    float*       C  = Cq;
    if (NQKV == 3) {
        if (blockIdx.z == 1)      { Bm = Bk; C = Ck; }
        else if (blockIdx.z == 2) { Bm = Bv; C = Cv; }
    }

    __shared__ float As[2][16][SLD];
    __shared__ float Bs[2][16][SLD];

    const int bm = blockIdx.y * 128;
    const int bn = blockIdx.x * 128;
    const int t  = threadIdx.x;
    const int ty = t >> 4, tx = t & 15;
    const int lr = t >> 2;          // 0..63
    const int lc = (t & 3) * 4;     // 0,4,8,12

    const float* Ap = A  + (size_t)(bm + lr) * K + lc;
    const float* Bp = Bm + (size_t)(bn + lr) * K + lc;

    float acc[8][8];
    #pragma unroll
    for (int i = 0; i < 8; i++)
        #pragma unroll
        for (int j = 0; j < 8; j++) acc[i][j] = 0.f;

    float4 pa0, pa1, pb0, pb1;

    // prologue: load K-step 0, stage into buffer 0
    pa0 = *(const float4*)(Ap);
    pa1 = *(const float4*)(Ap + (size_t)64 * K);
    pb0 = *(const float4*)(Bp);
    pb1 = *(const float4*)(Bp + (size_t)64 * K);
    {
        As[0][lc+0][lr] = pa0.x; As[0][lc+1][lr] = pa0.y;
        As[0][lc+2][lr] = pa0.z; As[0][lc+3][lr] = pa0.w;
        As[0][lc+0][lr+64] = pa1.x; As[0][lc+1][lr+64] = pa1.y;
        As[0][lc+2][lr+64] = pa1.z; As[0][lc+3][lr+64] = pa1.w;
        Bs[0][lc+0][lr] = pb0.x; Bs[0][lc+1][lr] = pb0.y;
        Bs[0][lc+2][lr] = pb0.z; Bs[0][lc+3][lr] = pb0.w;
        Bs[0][lc+0][lr+64] = pb1.x; Bs[0][lc+1][lr+64] = pb1.y;
        Bs[0][lc+2][lr+64] = pb1.z; Bs[0][lc+3][lr+64] = pb1.w;
    }
    __syncthreads();

    const int nk = K >> 4;
    #pragma unroll 1
    for (int ki = 0; ki < nk; ki++) {
        const int buf  = ki & 1;
        const int nbuf = buf ^ 1;
        const bool more = (ki + 1 < nk);

        // prefetch next K-step from global while computing current
        if (more) {
            const int k0 = (ki + 1) << 4;
            pa0 = *(const float4*)(Ap + k0);
            pa1 = *(const float4*)(Ap + (size_t)64 * K + k0);
            pb0 = *(const float4*)(Bp + k0);
            pb1 = *(const float4*)(Bp + (size_t)64 * K + k0);
        }

        #pragma unroll
        for (int kk = 0; kk < 16; kk++) {
            float4 a0 = *(const float4*)&As[buf][kk][ty * 4];
            float4 a1 = *(const float4*)&As[buf][kk][64 + ty * 4];
            float4 b0 = *(const float4*)&Bs[buf][kk][tx * 4];
            float4 b1 = *(const float4*)&Bs[buf][kk][64 + tx * 4];
            float a[8] = {a0.x,a0.y,a0.z,a0.w,a1.x,a1.y,a1.z,a1.w};
            float b[8] = {b0.x,b0.y,b0.z,b0.w,b1.x,b1.y,b1.z,b1.w};
            #pragma unroll
            for (int i = 0; i < 8; i++)
                #pragma unroll
                for (int j = 0; j < 8; j++)
                    acc[i][j] = fmaf(a[i], b[j], acc[i][j]);
        }

        if (more) {
            As[nbuf][lc+0][lr] = pa0.x; As[nbuf][lc+1][lr] = pa0.y;
            As[nbuf][lc+2][lr] = pa0.z; As[nbuf][lc+3][lr] = pa0.w;
            As[nbuf][lc+0][lr+64] = pa1.x; As[nbuf][lc+1][lr+64] = pa1.y;
            As[nbuf][lc+2][lr+64] = pa1.z; As[nbuf][lc+3][lr+64] = pa1.w;
            Bs[nbuf][lc+0][lr] = pb0.x; Bs[nbuf][lc+1][lr] = pb0.y;
            Bs[nbuf][lc+2][lr] = pb0.z; Bs[nbuf][lc+3][lr] = pb0.w;
            Bs[nbuf][lc+0][lr+64] = pb1.x; Bs[nbuf][lc+1][lr+64] = pb1.y;
            Bs[nbuf][lc+2][lr+64] = pb1.z; Bs[nbuf][lc+3][lr+64] = pb1.w;
            __syncthreads();
        }
    }

    // epilogue: vectorized float4 stores
    #pragma unroll
    for (int ih = 0; ih < 2; ih++) {
        #pragma unroll
        for (int i = 0; i < 4; i++) {
            const int row = bm + ih * 64 + ty * 4 + i;
            #pragma unroll
            for (int jh = 0; jh < 2; jh++) {
                const int col = bn + jh * 64 + tx * 4;
                float4 v = make_float4(acc[ih*4+i][jh*4+0], acc[ih*4+i][jh*4+1],
                                       acc[ih*4+i][jh*4+2], acc[ih*4+i][jh*4+3]);
                if (EPI >= EPI_BIAS) {
                    float4 bsv = *(const float4*)&bias[col];
                    v.x += bsv.x; v.y += bsv.y; v.z += bsv.z; v.w += bsv.w;
                }
                if (EPI == EPI_BIAS_GELU) {
                    v.x = 0.5f*v.x*(1.0f+erff(v.x*0.70710678118654752f));
                    v.y = 0.5f*v.y*(1.0f+erff(v.y*0.70710678118654752f));
                    v.z = 0.5f*v.z*(1.0f+erff(v.z*0.70710678118654752f));
                    v.w = 0.5f*v.w*(1.0f+erff(v.w*0.70710678118654752f));
                }
                if (EPI == EPI_BIAS_RES) {
                    float4 rv = *(const float4*)&R[(size_t)row * N + col];
                    v.x += rv.x; v.y += rv.y; v.z += rv.z; v.w += rv.w;
                }
                *(float4*)&C[(size_t)row * N + col] = v;
            }
        }
    }
}

// ---------------------------------------------------------------------------
// Flash attention (fp32, causal, online softmax)
// Block: 256 threads, 64 queries of one (b,h); 64-wide K/V tiles
// smem: Qs[64][68], Kt[64][68] (d-major), Vs[64][68], Ps[64][68]  (~69.6 KB dyn)
// ---------------------------------------------------------------------------
#define LDA 68
__global__ __launch_bounds__(256, 2)
void flash_kernel(const float* __restrict__ Qg, const float* __restrict__ Kg,
                  const float* __restrict__ Vg, float* __restrict__ Og)
{
    extern __shared__ float sm[];
    float* Qs = sm;
    float* Kt = sm + 64 * LDA;
    float* Vs = sm + 2 * 64 * LDA;
    float* Ps = sm + 3 * 64 * LDA;

    const int qt = blockIdx.x, h = blockIdx.y, b = blockIdx.z;
    const int q0 = qt * 64;
    const int t  = threadIdx.x;
    const int ty = t >> 4, tx = t & 15;
    const int lr = t >> 2, lq = t & 3;
    const size_t base = (size_t)b * Ss * Ee + h * Dd;

    // Load Q tile once
    {
        const float* qp = Qg + base + (size_t)(q0 + lr) * Ee;
        #pragma unroll
        for (int c = 0; c < 4; c++) {
            const int col = (c * 4 + lq) * 4;
            *(float4*)&Qs[lr * LDA + col] = *(const float4*)(qp + col);
        }
    }

    float m[4], l[4], o[4][4];
    #pragma unroll
    for (int i = 0; i < 4; i++) {
        m[i] = -INFINITY; l[i] = 0.f;
        #pragma unroll
        for (int j = 0; j < 4; j++) o[i][j] = 0.f;
    }
    __syncthreads();

    for (int kt = 0; kt <= qt; kt++) {
        const int k0 = kt * 64;
        // Load K (transposed -> d-major) and V (row-major)
        {
            const float* kp = Kg + base + (size_t)(k0 + lr) * Ee;
            const float* vp = Vg + base + (size_t)(k0 + lr) * Ee;
            #pragma unroll
            for (int c = 0; c < 4; c++) {
                const int col = (c * 4 + lq) * 4;
                float4 kv = *(const float4*)(kp + col);
                Kt[(col + 0) * LDA + lr] = kv.x;
                Kt[(col + 1) * LDA + lr] = kv.y;
                Kt[(col + 2) * LDA + lr] = kv.z;
                Kt[(col + 3) * LDA + lr] = kv.w;
                *(float4*)&Vs[lr * LDA + col] = *(const float4*)(vp + col);
            }
        }
        __syncthreads();

        // Scores: s[i][j] = sum_d Q[i][d] * K[j][d]
        float s[4][4];
        #pragma unroll
        for (int i = 0; i < 4; i++)
            #pragma unroll
            for (int j = 0; j < 4; j++) s[i][j] = 0.f;

        #pragma unroll
        for (int d4 = 0; d4 < 16; d4++) {
            float qa[4][4], ka[4][4];
            #pragma unroll
            for (int i = 0; i < 4; i++) {
                float4 v = *(const float4*)&Qs[(ty * 4 + i) * LDA + d4 * 4];
                qa[i][0] = v.x; qa[i][1] = v.y; qa[i][2] = v.z; qa[i][3] = v.w;
            }
            #pragma unroll
            for (int dd = 0; dd < 4; dd++) {
                float4 v = *(const float4*)&Kt[(d4 * 4 + dd) * LDA + tx * 4];
                ka[dd][0] = v.x; ka[dd][1] = v.y; ka[dd][2] = v.z; ka[dd][3] = v.w;
            }
            #pragma unroll
            for (int dd = 0; dd < 4; dd++)
                #pragma unroll
                for (int i = 0; i < 4; i++)
                    #pragma unroll
                    for (int j = 0; j < 4; j++)
                        s[i][j] = fmaf(qa[i][dd], ka[dd][j], s[i][j]);
        }

        // Scale + causal mask + online softmax update
        const bool diag = (kt == qt);
        #pragma unroll
        for (int i = 0; i < 4; i++) {
            const int qi = ty * 4 + i;   // local query row
            #pragma unroll
            for (int j = 0; j < 4; j++) {
                float val = s[i][j] * 0.125f;    // 1/sqrt(64)
                if (diag && (tx * 4 + j) > qi) val = -1e30f;
                s[i][j] = val;
            }
            float tm = fmaxf(fmaxf(s[i][0], s[i][1]), fmaxf(s[i][2], s[i][3]));
            #pragma unroll
            for (int off = 8; off; off >>= 1)
                tm = fmaxf(tm, __shfl_xor_sync(0xffffffffu, tm, off));
            const float mn    = fmaxf(m[i], tm);
            const float alpha = __expf(m[i] - mn);
            float rs = 0.f;
            #pragma unroll
            for (int j = 0; j < 4; j++) {
                float p = __expf(s[i][j] - mn);
                s[i][j] = p; rs += p;
            }
            #pragma unroll
            for (int off = 8; off; off >>= 1)
                rs += __shfl_xor_sync(0xffffffffu, rs, off);
            l[i] = l[i] * alpha + rs;
            m[i] = mn;
            #pragma unroll
            for (int j = 0; j < 4; j++) o[i][j] *= alpha;
        }

        // Store P tile
        #pragma unroll
        for (int i = 0; i < 4; i++)
            *(float4*)&Ps[(ty * 4 + i) * LDA + tx * 4] =
                make_float4(s[i][0], s[i][1], s[i][2], s[i][3]);
        __syncthreads();

        // O += P @ V
        #pragma unroll
        for (int j4 = 0; j4 < 16; j4++) {
            float pa[4][4], va[4][4];
            #pragma unroll
            for (int i = 0; i < 4; i++) {
                float4 v = *(const float4*)&Ps[(ty * 4 + i) * LDA + j4 * 4];
                pa[i][0] = v.x; pa[i][1] = v.y; pa[i][2] = v.z; pa[i][3] = v.w;
            }
            #pragma unroll
            for (int jj = 0; jj < 4; jj++) {
                float4 v = *(const float4*)&Vs[(j4 * 4 + jj) * LDA + tx * 4];
                va[jj][0] = v.x; va[jj][1] = v.y; va[jj][2] = v.z; va[jj][3] = v.w;
            }
            #pragma unroll
            for (int jj = 0; jj < 4; jj++)
                #pragma unroll
                for (int i = 0; i < 4; i++)
                    #pragma unroll
                    for (int d = 0; d < 4; d++)
                        o[i][d] = fmaf(pa[i][jj], va[jj][d], o[i][d]);
        }
        __syncthreads();
    }

    // Normalize + write
    #pragma unroll
    for (int i = 0; i < 4; i++) {
        const float inv = 1.0f / l[i];
        const int row = q0 + ty * 4 + i;
        float* op = Og + base + (size_t)row * Ee + tx * 4;
        op[0] = o[i][0] * inv; op[1] = o[i][1] * inv;
        op[2] = o[i][2] * inv; op[3] = o[i][3] * inv;
    }
}

// ---------------------------------------------------------------------------
// Launch: LN -> fused QKV GEMM -> flash attn -> O proj(+res) -> LN
//         -> FFN1(GELU) -> FFN2(+res)
// ---------------------------------------------------------------------------
extern "C" void kernel_launch(void* const* d_in, const int* in_sizes, int n_in,
                              void* d_out, int out_size)
{
    const float* x     = (const float*)d_in[0];
    const float* wq    = (const float*)d_in[1];
    const float* wk    = (const float*)d_in[2];
    const float* wv    = (const float*)d_in[3];
    const float* wo    = (const float*)d_in[4];
    const float* bo    = (const float*)d_in[5];
    const float* w1    = (const float*)d_in[6];
    const float* b1    = (const float*)d_in[7];
    const float* w2    = (const float*)d_in[8];
    const float* b2    = (const float*)d_in[9];
    const float* gamma = (const float*)d_in[10];
    const float* beta  = (const float*)d_in[11];
    float* out = (float*)d_out;

    float *xn, *q, *k, *v, *at, *res, *y, *hb;
    cudaGetSymbolAddress((void**)&xn,  g_xn);
    cudaGetSymbolAddress((void**)&q,   g_q);
    cudaGetSymbolAddress((void**)&k,   g_k);
    cudaGetSymbolAddress((void**)&v,   g_v);
    cudaGetSymbolAddress((void**)&at,  g_at);
    cudaGetSymbolAddress((void**)&res, g_res);
    cudaGetSymbolAddress((void**)&y,   g_y);
    cudaGetSymbolAddress((void**)&hb,  g_h);

    const dim3 gqkv(Ee / 128, Mrows / 128, 3);   // (6, 32, 3) fused QKV
    const dim3 g768(Ee / 128, Mrows / 128);      // (6, 32)
    const dim3 g3072(FFf / 128, Mrows / 128);    // (24, 32)
    const int  smemFA = 4 * 64 * LDA * (int)sizeof(float);

    cudaFuncSetAttribute(flash_kernel, cudaFuncAttributeMaxDynamicSharedMemorySize, smemFA);

    ln_kernel<<<Mrows, 256>>>(x, gamma, beta, xn);

    sgemm_bt<EPI_NONE, 3><<<gqkv, 256>>>(xn, wq, wk, wv, nullptr, nullptr,
                                         q, k, v, Mrows, Ee, Ee);

    flash_kernel<<<dim3(Ss / 64, Hh, Bb), 256, smemFA>>>(q, k, v, at);

    sgemm_bt<EPI_BIAS_RES, 1><<<g768, 256>>>(at, wo, wo, wo, bo, x,
                                             res, res, res, Mrows, Ee, Ee);

    ln_kernel<<<Mrows, 256>>>(res, gamma, beta, y);

    sgemm_bt<EPI_BIAS_GELU, 1><<<g3072, 256>>>(y, w1, w1, w1, b1, nullptr,
                                               hb, hb, hb, Mrows, FFf, Ee);
    sgemm_bt<EPI_BIAS_RES, 1><<<g768, 256>>>(hb, w2, w2, w2, b2, res,
                                             out, out, out, Mrows, Ee, FFf);
}

// round 4
// speedup vs baseline: 2.2363x; 1.8575x over previous
#include <cuda_runtime.h>
#include <math.h>
#include <stdint.h>

// Problem constants
#define Bb   2
#define Ss   2048
#define Ee   768
#define Hh   12
#define Dd   64
#define FFf  3072
#define Mrows (Bb*Ss)   // 4096

// ---------------------------------------------------------------------------
// Scratch (static device globals; no runtime allocation allowed)
// ---------------------------------------------------------------------------
__device__ float g_xn [Mrows*Ee];
__device__ float g_q  [Mrows*Ee];
__device__ float g_k  [Mrows*Ee];
__device__ float g_v  [Mrows*Ee];
__device__ float g_at [Mrows*Ee];
__device__ float g_res[Mrows*Ee];
__device__ float g_y  [Mrows*Ee];
__device__ float g_h  [Mrows*FFf];

// ---------------------------------------------------------------------------
// Helpers: cp.async (sm_80 baseline) + tf32 mma.sync (sm_80 baseline)
// ---------------------------------------------------------------------------
__device__ __forceinline__ uint32_t smem_u32(const void* p) {
    uint32_t a;
    asm("{ .reg .u64 t; cvta.to.shared.u64 t, %1; cvt.u32.u64 %0, t; }"
        : "=r"(a) : "l"(p));
    return a;
}
__device__ __forceinline__ void cp16(uint32_t dst, const void* src) {
    asm volatile("cp.async.cg.shared.global [%0], [%1], 16;"
                 :: "r"(dst), "l"(src));
}
#define CP_COMMIT() asm volatile("cp.async.commit_group;" ::: "memory")
#define CP_WAIT(n)  asm volatile("cp.async.wait_group %0;" :: "n"(n) : "memory")

// D += A(16x8,row) * B(8x8,col as B^T rows)  tf32 inputs (raw fp32 bits)
__device__ __forceinline__ void mma_tf32(float* c, const uint32_t* a,
                                         uint32_t b0, uint32_t b1) {
    asm volatile(
        "mma.sync.aligned.m16n8k8.row.col.f32.tf32.tf32.f32 "
        "{%0,%1,%2,%3}, {%4,%5,%6,%7}, {%8,%9}, {%0,%1,%2,%3};"
        : "+f"(c[0]), "+f"(c[1]), "+f"(c[2]), "+f"(c[3])
        : "r"(a[0]), "r"(a[1]), "r"(a[2]), "r"(a[3]), "r"(b0), "r"(b1));
}

// ---------------------------------------------------------------------------
// LayerNorm: one block (256 threads) per row of 768
// ---------------------------------------------------------------------------
__global__ void ln_kernel(const float* __restrict__ X,
                          const float* __restrict__ gamma,
                          const float* __restrict__ beta,
                          float* __restrict__ Y)
{
    const int row = blockIdx.x;
    const float* x = X + (size_t)row * Ee;
    float*       y = Y + (size_t)row * Ee;
    const int t = threadIdx.x;

    float v0 = x[t], v1 = x[t + 256], v2 = x[t + 512];
    float s  = v0 + v1 + v2;

    __shared__ float red[8];
    #pragma unroll
    for (int off = 16; off; off >>= 1) s += __shfl_xor_sync(0xffffffffu, s, off);
    if ((t & 31) == 0) red[t >> 5] = s;
    __syncthreads();
    if (t < 8) {
        float r = red[t];
        #pragma unroll
        for (int off = 4; off; off >>= 1) r += __shfl_xor_sync(0xffu, r, off);
        if (t == 0) red[0] = r;
    }
    __syncthreads();
    const float mu = red[0] * (1.0f / Ee);
    __syncthreads();

    float d0 = v0 - mu, d1 = v1 - mu, d2 = v2 - mu;
    float q  = d0*d0 + d1*d1 + d2*d2;
    #pragma unroll
    for (int off = 16; off; off >>= 1) q += __shfl_xor_sync(0xffffffffu, q, off);
    if ((t & 31) == 0) red[t >> 5] = q;
    __syncthreads();
    if (t < 8) {
        float r = red[t];
        #pragma unroll
        for (int off = 4; off; off >>= 1) r += __shfl_xor_sync(0xffu, r, off);
        if (t == 0) red[0] = r;
    }
    __syncthreads();
    const float inv = rsqrtf(red[0] * (1.0f / Ee) + 1e-5f);

    y[t      ] = d0 * inv * gamma[t      ] + beta[t      ];
    y[t + 256] = d1 * inv * gamma[t + 256] + beta[t + 256];
    y[t + 512] = d2 * inv * gamma[t + 512] + beta[t + 512];
}

// ---------------------------------------------------------------------------
// tf32 tensor-core GEMM: C[M,N] = A[M,K] * B[N,K]^T (+ epilogue)
// CTA 128x128, 8 warps (4x2), warp tile 32x64, m16n8k8 HMMA.
// K-chunk 64, double-buffered smem filled by cp.async.
// ---------------------------------------------------------------------------
enum { EPI_NONE = 0, EPI_BIAS = 1, EPI_BIAS_GELU = 2, EPI_BIAS_RES = 3 };

#define PITCH   68                      // floats per smem row (64 + 4 pad)
#define TILEF   (128*PITCH)             // floats per matrix per buffer
#define SMEMF   (4*TILEF)               // A0,A1,B0,B1
#define SMEMB   (SMEMF*4)               // bytes (139264)

template <int EPI, int NQKV>
__global__ __launch_bounds__(256, 1)
void gemm_mma(const float* __restrict__ A,
              const float* __restrict__ Bq, const float* __restrict__ Bk,
              const float* __restrict__ Bv,
              const float* __restrict__ bias, const float* __restrict__ R,
              float* __restrict__ Cq, float* __restrict__ Ck,
              float* __restrict__ Cv,
              int M, int N, int K)
{
    const float* Bm = Bq;
    float*       C  = Cq;
    if (NQKV == 3) {
        if (blockIdx.z == 1)      { Bm = Bk; C = Ck; }
        else if (blockIdx.z == 2) { Bm = Bv; C = Cv; }
    }

    extern __shared__ float sm[];
    float* Asm = sm;              // [2][128][PITCH]
    float* Bsm = sm + 2 * TILEF;  // [2][128][PITCH]

    const int t    = threadIdx.x;
    const int lane = t & 31;
    const int wid  = t >> 5;
    const int wr   = wid & 3;            // warp row (m)
    const int wc   = wid >> 2;           // warp col (n)
    const int mr   = wr * 32;
    const int nc0  = wc * 64;
    const int g    = lane >> 2;          // group id 0..7
    const int tg   = lane & 3;           // thread-in-group 0..3
    const int r0   = t >> 4;             // 0..15
    const int c4   = t & 15;             // float4 col within K-chunk

    const int bm = blockIdx.y * 128;
    const int bn = blockIdx.x * 128;

    float c[2][8][4];
    #pragma unroll
    for (int mt = 0; mt < 2; mt++)
        #pragma unroll
        for (int nt = 0; nt < 8; nt++)
            #pragma unroll
            for (int i = 0; i < 4; i++) c[mt][nt][i] = 0.f;

    const uint32_t sA = smem_u32(Asm);
    const uint32_t sB = smem_u32(Bsm);

    // issue one K-chunk's cp.async loads into buffer (ci&1)
    auto issue = [&](int ci) {
        const int buf = ci & 1;
        const int k0  = ci << 6;
        const uint32_t dA = sA + (uint32_t)buf * TILEF * 4;
        const uint32_t dB = sB + (uint32_t)buf * TILEF * 4;
        #pragma unroll
        for (int p = 0; p < 8; p++) {
            const int row = p * 16 + r0;
            const uint32_t so = (uint32_t)(row * PITCH + c4 * 4) * 4;
            cp16(dA + so, A  + (size_t)(bm + row) * K + k0 + c4 * 4);
            cp16(dB + so, Bm + (size_t)(bn + row) * K + k0 + c4 * 4);
        }
        CP_COMMIT();
    };

    const int nchunk = K >> 6;
    issue(0);

    #pragma unroll 1
    for (int ci = 0; ci < nchunk; ci++) {
        if (ci + 1 < nchunk) { issue(ci + 1); CP_WAIT(1); }
        else                 { CP_WAIT(0); }
        __syncthreads();

        const float* sa = Asm + (ci & 1) * TILEF;
        const float* sb = Bsm + (ci & 1) * TILEF;

        #pragma unroll
        for (int kk = 0; kk < 8; kk++) {
            const int kb = kk * 8;
            uint32_t a[2][4];
            #pragma unroll
            for (int mt = 0; mt < 2; mt++) {
                const float* p0 = sa + (mr + mt * 16 + g) * PITCH + kb + tg;
                const float* p1 = p0 + 8 * PITCH;
                a[mt][0] = __float_as_uint(p0[0]);
                a[mt][1] = __float_as_uint(p1[0]);
                a[mt][2] = __float_as_uint(p0[4]);
                a[mt][3] = __float_as_uint(p1[4]);
            }
            #pragma unroll
            for (int nt = 0; nt < 8; nt++) {
                const float* q0 = sb + (nc0 + nt * 8 + g) * PITCH + kb + tg;
                const uint32_t b0 = __float_as_uint(q0[0]);
                const uint32_t b1 = __float_as_uint(q0[4]);
                mma_tf32(c[0][nt], a[0], b0, b1);
                mma_tf32(c[1][nt], a[1], b0, b1);
            }
        }
        __syncthreads();
    }

    // Epilogue: c[mt][nt]: rows bm+mr+mt*16+{g, g+8}; cols bn+nc0+nt*8+2*tg+{0,1}
    #pragma unroll
    for (int mt = 0; mt < 2; mt++) {
        #pragma unroll
        for (int half = 0; half < 2; half++) {
            const int row = bm + mr + mt * 16 + g + half * 8;
            #pragma unroll
            for (int nt = 0; nt < 8; nt++) {
                const int col = bn + nc0 + nt * 8 + 2 * tg;
                float2 v = make_float2(c[mt][nt][half * 2 + 0],
                                       c[mt][nt][half * 2 + 1]);
                if (EPI >= EPI_BIAS) {
                    float2 bb = *(const float2*)(bias + col);
                    v.x += bb.x; v.y += bb.y;
                }
                if (EPI == EPI_BIAS_GELU) {
                    v.x = 0.5f * v.x * (1.0f + erff(v.x * 0.70710678118654752f));
                    v.y = 0.5f * v.y * (1.0f + erff(v.y * 0.70710678118654752f));
                }
                if (EPI == EPI_BIAS_RES) {
                    float2 rr = *(const float2*)(R + (size_t)row * N + col);
                    v.x += rr.x; v.y += rr.y;
                }
                *(float2*)(C + (size_t)row * N + col) = v;
            }
        }
    }
}

// ---------------------------------------------------------------------------
// Flash attention (fp32, causal, online softmax) — unchanged
// ---------------------------------------------------------------------------
#define LDA 68
__global__ __launch_bounds__(256, 2)
void flash_kernel(const float* __restrict__ Qg, const float* __restrict__ Kg,
                  const float* __restrict__ Vg, float* __restrict__ Og)
{
    extern __shared__ float sm[];
    float* Qs = sm;
    float* Kt = sm + 64 * LDA;
    float* Vs = sm + 2 * 64 * LDA;
    float* Ps = sm + 3 * 64 * LDA;

    const int qt = blockIdx.x, h = blockIdx.y, b = blockIdx.z;
    const int q0 = qt * 64;
    const int t  = threadIdx.x;
    const int ty = t >> 4, tx = t & 15;
    const int lr = t >> 2, lq = t & 3;
    const size_t base = (size_t)b * Ss * Ee + h * Dd;

    {
        const float* qp = Qg + base + (size_t)(q0 + lr) * Ee;
        #pragma unroll
        for (int c = 0; c < 4; c++) {
            const int col = (c * 4 + lq) * 4;
            *(float4*)&Qs[lr * LDA + col] = *(const float4*)(qp + col);
        }
    }

    float m[4], l[4], o[4][4];
    #pragma unroll
    for (int i = 0; i < 4; i++) {
        m[i] = -INFINITY; l[i] = 0.f;
        #pragma unroll
        for (int j = 0; j < 4; j++) o[i][j] = 0.f;
    }
    __syncthreads();

    for (int kt = 0; kt <= qt; kt++) {
        const int k0 = kt * 64;
        {
            const float* kp = Kg + base + (size_t)(k0 + lr) * Ee;
            const float* vp = Vg + base + (size_t)(k0 + lr) * Ee;
            #pragma unroll
            for (int c = 0; c < 4; c++) {
                const int col = (c * 4 + lq) * 4;
                float4 kv = *(const float4*)(kp + col);
                Kt[(col + 0) * LDA + lr] = kv.x;
                Kt[(col + 1) * LDA + lr] = kv.y;
                Kt[(col + 2) * LDA + lr] = kv.z;
                Kt[(col + 3) * LDA + lr] = kv.w;
                *(float4*)&Vs[lr * LDA + col] = *(const float4*)(vp + col);
            }
        }
        __syncthreads();

        float s[4][4];
        #pragma unroll
        for (int i = 0; i < 4; i++)
            #pragma unroll
            for (int j = 0; j < 4; j++) s[i][j] = 0.f;

        #pragma unroll
        for (int d4 = 0; d4 < 16; d4++) {
            float qa[4][4], ka[4][4];
            #pragma unroll
            for (int i = 0; i < 4; i++) {
                float4 v = *(const float4*)&Qs[(ty * 4 + i) * LDA + d4 * 4];
                qa[i][0] = v.x; qa[i][1] = v.y; qa[i][2] = v.z; qa[i][3] = v.w;
            }
            #pragma unroll
            for (int dd = 0; dd < 4; dd++) {
                float4 v = *(const float4*)&Kt[(d4 * 4 + dd) * LDA + tx * 4];
                ka[dd][0] = v.x; ka[dd][1] = v.y; ka[dd][2] = v.z; ka[dd][3] = v.w;
            }
            #pragma unroll
            for (int dd = 0; dd < 4; dd++)
                #pragma unroll
                for (int i = 0; i < 4; i++)
                    #pragma unroll
                    for (int j = 0; j < 4; j++)
                        s[i][j] = fmaf(qa[i][dd], ka[dd][j], s[i][j]);
        }

        const bool diag = (kt == qt);
        #pragma unroll
        for (int i = 0; i < 4; i++) {
            const int qi = ty * 4 + i;
            #pragma unroll
            for (int j = 0; j < 4; j++) {
                float val = s[i][j] * 0.125f;
                if (diag && (tx * 4 + j) > qi) val = -1e30f;
                s[i][j] = val;
            }
            float tm = fmaxf(fmaxf(s[i][0], s[i][1]), fmaxf(s[i][2], s[i][3]));
            #pragma unroll
            for (int off = 8; off; off >>= 1)
                tm = fmaxf(tm, __shfl_xor_sync(0xffffffffu, tm, off));
            const float mn    = fmaxf(m[i], tm);
            const float alpha = __expf(m[i] - mn);
            float rs = 0.f;
            #pragma unroll
            for (int j = 0; j < 4; j++) {
                float p = __expf(s[i][j] - mn);
                s[i][j] = p; rs += p;
            }
            #pragma unroll
            for (int off = 8; off; off >>= 1)
                rs += __shfl_xor_sync(0xffffffffu, rs, off);
            l[i] = l[i] * alpha + rs;
            m[i] = mn;
            #pragma unroll
            for (int j = 0; j < 4; j++) o[i][j] *= alpha;
        }

        #pragma unroll
        for (int i = 0; i < 4; i++)
            *(float4*)&Ps[(ty * 4 + i) * LDA + tx * 4] =
                make_float4(s[i][0], s[i][1], s[i][2], s[i][3]);
        __syncthreads();

        #pragma unroll
        for (int j4 = 0; j4 < 16; j4++) {
            float pa[4][4], va[4][4];
            #pragma unroll
            for (int i = 0; i < 4; i++) {
                float4 v = *(const float4*)&Ps[(ty * 4 + i) * LDA + j4 * 4];
                pa[i][0] = v.x; pa[i][1] = v.y; pa[i][2] = v.z; pa[i][3] = v.w;
            }
            #pragma unroll
            for (int jj = 0; jj < 4; jj++) {
                float4 v = *(const float4*)&Vs[(j4 * 4 + jj) * LDA + tx * 4];
                va[jj][0] = v.x; va[jj][1] = v.y; va[jj][2] = v.z; va[jj][3] = v.w;
            }
            #pragma unroll
            for (int jj = 0; jj < 4; jj++)
                #pragma unroll
                for (int i = 0; i < 4; i++)
                    #pragma unroll
                    for (int d = 0; d < 4; d++)
                        o[i][d] = fmaf(pa[i][jj], va[jj][d], o[i][d]);
        }
        __syncthreads();
    }

    #pragma unroll
    for (int i = 0; i < 4; i++) {
        const float inv = 1.0f / l[i];
        const int row = q0 + ty * 4 + i;
        float* op = Og + base + (size_t)row * Ee + tx * 4;
        op[0] = o[i][0] * inv; op[1] = o[i][1] * inv;
        op[2] = o[i][2] * inv; op[3] = o[i][3] * inv;
    }
}

// ---------------------------------------------------------------------------
// Launch
// ---------------------------------------------------------------------------
extern "C" void kernel_launch(void* const* d_in, const int* in_sizes, int n_in,
                              void* d_out, int out_size)
{
    const float* x     = (const float*)d_in[0];
    const float* wq    = (const float*)d_in[1];
    const float* wk    = (const float*)d_in[2];
    const float* wv    = (const float*)d_in[3];
    const float* wo    = (const float*)d_in[4];
    const float* bo    = (const float*)d_in[5];
    const float* w1    = (const float*)d_in[6];
    const float* b1    = (const float*)d_in[7];
    const float* w2    = (const float*)d_in[8];
    const float* b2    = (const float*)d_in[9];
    const float* gamma = (const float*)d_in[10];
    const float* beta  = (const float*)d_in[11];
    float* out = (float*)d_out;

    float *xn, *q, *k, *v, *at, *res, *y, *hb;
    cudaGetSymbolAddress((void**)&xn,  g_xn);
    cudaGetSymbolAddress((void**)&q,   g_q);
    cudaGetSymbolAddress((void**)&k,   g_k);
    cudaGetSymbolAddress((void**)&v,   g_v);
    cudaGetSymbolAddress((void**)&at,  g_at);
    cudaGetSymbolAddress((void**)&res, g_res);
    cudaGetSymbolAddress((void**)&y,   g_y);
    cudaGetSymbolAddress((void**)&hb,  g_h);

    const dim3 gqkv(Ee / 128, Mrows / 128, 3);
    const dim3 g768(Ee / 128, Mrows / 128);
    const dim3 g3072(FFf / 128, Mrows / 128);
    const int  smemFA = 4 * 64 * LDA * (int)sizeof(float);

    cudaFuncSetAttribute(flash_kernel, cudaFuncAttributeMaxDynamicSharedMemorySize, smemFA);
    cudaFuncSetAttribute(gemm_mma<EPI_NONE,3>,      cudaFuncAttributeMaxDynamicSharedMemorySize, SMEMB);
    cudaFuncSetAttribute(gemm_mma<EPI_BIAS_RES,1>,  cudaFuncAttributeMaxDynamicSharedMemorySize, SMEMB);
    cudaFuncSetAttribute(gemm_mma<EPI_BIAS_GELU,1>, cudaFuncAttributeMaxDynamicSharedMemorySize, SMEMB);

    ln_kernel<<<Mrows, 256>>>(x, gamma, beta, xn);

    gemm_mma<EPI_NONE,3><<<gqkv, 256, SMEMB>>>(xn, wq, wk, wv, nullptr, nullptr,
                                               q, k, v, Mrows, Ee, Ee);

    flash_kernel<<<dim3(Ss / 64, Hh, Bb), 256, smemFA>>>(q, k, v, at);

    gemm_mma<EPI_BIAS_RES,1><<<g768, 256, SMEMB>>>(at, wo, wo, wo, bo, x,
                                                   res, res, res, Mrows, Ee, Ee);

    ln_kernel<<<Mrows, 256>>>(res, gamma, beta, y);

    gemm_mma<EPI_BIAS_GELU,1><<<g3072, 256, SMEMB>>>(y, w1, w1, w1, b1, nullptr,
                                                     hb, hb, hb, Mrows, FFf, Ee);
    gemm_mma<EPI_BIAS_RES,1><<<g768, 256, SMEMB>>>(hb, w2, w2, w2, b2, res,
                                                   out, out, out, Mrows, Ee, FFf);
}